// round 5
// baseline (speedup 1.0000x reference)
#include <cuda_runtime.h>
#include <cstdint>
#include <math.h>

#define NCH     131072
#define NSTEPS  60
#define HD      128
#define WARPS   4
#define PAIRS   2                       // f32x2 chain-pairs per warp
#define THREADS (WARPS*32)
#define CH_PER_CTA (WARPS*PAIRS*2)      // 16 chains per CTA
#define GRID    (NCH/CH_PER_CTA)        // 8192 CTAs

typedef unsigned long long u64;

// ---------------- smem byte offsets ----------------
#define OFF_W2  0
#define OFF_W3  65536
#define OFF_W4  131072
#define OFF_W1  196608
#define OFF_B1  197632
#define OFF_B2  198144
#define OFF_B3  198656
#define OFF_B4  199168
#define OFF_W5  199680
#define OFF_STG 200192                  // u64[WARPS*PAIRS*3*HD] = 24576 B
#define OFF_XS  224768                  // u64[WARPS*PAIRS*2]
#define SMEM_BYTES 224896

// ---------------- f32x2 helpers (packed fp32, sm_100+) ----------------
__device__ __forceinline__ u64 pk(float a, float b) {
    u64 r; asm("mov.b64 %0,{%1,%2};" : "=l"(r) : "f"(a), "f"(b)); return r;
}
__device__ __forceinline__ u64 dup(float a) {
    u64 r; asm("mov.b64 %0,{%1,%1};" : "=l"(r) : "f"(a)); return r;
}
__device__ __forceinline__ void upk(u64 v, float& a, float& b) {
    asm("mov.b64 {%0,%1},%2;" : "=f"(a), "=f"(b) : "l"(v));
}
__device__ __forceinline__ u64 fma2(u64 a, u64 b, u64 c) {
    u64 r; asm("fma.rn.f32x2 %0,%1,%2,%3;" : "=l"(r) : "l"(a), "l"(b), "l"(c)); return r;
}
__device__ __forceinline__ u64 mul2(u64 a, u64 b) {
    u64 r; asm("mul.rn.f32x2 %0,%1,%2;" : "=l"(r) : "l"(a), "l"(b)); return r;
}

// silu(z) and silu'(z) on a packed pair.
// s = sigmoid(z), h = z*s, d = s + (z*s)*(1-s)
__device__ __forceinline__ void silu2(u64 z, u64& h, u64& d) {
    float za, zb; upk(z, za, zb);
    float sa = __fdividef(1.0f, 1.0f + __expf(-za));
    float sb = __fdividef(1.0f, 1.0f + __expf(-zb));
    float ha = za * sa, hb = zb * sb;
    h = pk(ha, hb);
    d = pk(fmaf(ha, 1.0f - sa, sa), fmaf(hb, 1.0f - sb, sb));
}

__device__ __forceinline__ void st4(u64* d, const u64* v) {
    ulonglong2 a; a.x = v[0]; a.y = v[1];
    ulonglong2 b; b.x = v[2]; b.y = v[3];
    ((ulonglong2*)d)[0] = a;
    ((ulonglong2*)d)[1] = b;
}

__device__ __forceinline__ void cpy(float* dst, const float* src, int n, int tid) {
    const float4* s = (const float4*)src;
    float4* d = (float4*)dst;
    for (int i = tid; i < n / 4; i += THREADS) d[i] = s[i];
}

// One 128->128 dense layer on the (h, Jx, Jy) streams for PAIRS chain-pairs.
// LAST: instead of staging outputs, fold Jx/Jy against w5 into pg (per-pair grad accum).
template <bool LAST>
__device__ __forceinline__ void dense(const float* __restrict__ W,
                                      const float* __restrict__ bvec,
                                      const float* __restrict__ w5s,
                                      u64* __restrict__ stg,
                                      int j0, u64 (&pg)[PAIRS][2]) {
    u64 ah[PAIRS][4], ax[PAIRS][4], ay[PAIRS][4];
#pragma unroll
    for (int p = 0; p < PAIRS; p++)
#pragma unroll
        for (int u = 0; u < 4; u++) {
            ah[p][u] = dup(bvec[j0 + u]);
            ax[p][u] = 0ull;
            ay[p][u] = 0ull;
        }

#pragma unroll 4
    for (int i = 0; i < HD; i++) {
        float4 wv = *(const float4*)(W + i * HD + j0);
        u64 w0 = dup(wv.x), w1 = dup(wv.y), w2 = dup(wv.z), w3 = dup(wv.w);
#pragma unroll
        for (int p = 0; p < PAIRS; p++) {
            u64 hb = stg[(p * 3 + 0) * HD + i];
            u64 xb = stg[(p * 3 + 1) * HD + i];
            u64 yb = stg[(p * 3 + 2) * HD + i];
            ah[p][0] = fma2(hb, w0, ah[p][0]); ah[p][1] = fma2(hb, w1, ah[p][1]);
            ah[p][2] = fma2(hb, w2, ah[p][2]); ah[p][3] = fma2(hb, w3, ah[p][3]);
            ax[p][0] = fma2(xb, w0, ax[p][0]); ax[p][1] = fma2(xb, w1, ax[p][1]);
            ax[p][2] = fma2(xb, w2, ax[p][2]); ax[p][3] = fma2(xb, w3, ax[p][3]);
            ay[p][0] = fma2(yb, w0, ay[p][0]); ay[p][1] = fma2(yb, w1, ay[p][1]);
            ay[p][2] = fma2(yb, w2, ay[p][2]); ay[p][3] = fma2(yb, w3, ay[p][3]);
        }
    }
    __syncwarp();   // all lanes done READING stage before anyone overwrites it

#pragma unroll
    for (int p = 0; p < PAIRS; p++) {
        u64 ho[4], xo[4], yo[4];
#pragma unroll
        for (int u = 0; u < 4; u++) {
            u64 h, d;
            silu2(ah[p][u], h, d);
            if (LAST) {
                u64 w5d = dup(w5s[j0 + u]);
                pg[p][0] = fma2(mul2(d, ax[p][u]), w5d, pg[p][0]);
                pg[p][1] = fma2(mul2(d, ay[p][u]), w5d, pg[p][1]);
            } else {
                ho[u] = h;
                xo[u] = mul2(d, ax[p][u]);
                yo[u] = mul2(d, ay[p][u]);
            }
        }
        if (!LAST) {
            st4(stg + (p * 3 + 0) * HD + j0, ho);
            st4(stg + (p * 3 + 1) * HD + j0, xo);
            st4(stg + (p * 3 + 2) * HD + j0, yo);
        }
    }
    if (!LAST) __syncwarp();   // writes visible before next layer reads
}

__global__ void __launch_bounds__(THREADS, 1)
EBMb_17360257810670_kernel(const float* __restrict__ x0g,
                           const float* __restrict__ w1g, const float* __restrict__ b1g,
                           const float* __restrict__ w2g, const float* __restrict__ b2g,
                           const float* __restrict__ w3g, const float* __restrict__ b3g,
                           const float* __restrict__ w4g, const float* __restrict__ b4g,
                           const float* __restrict__ w5g,
                           const float* __restrict__ noise,
                           float* __restrict__ out) {
    extern __shared__ char smem[];
    float* w2s = (float*)(smem + OFF_W2);
    float* w3s = (float*)(smem + OFF_W3);
    float* w4s = (float*)(smem + OFF_W4);
    float* w1s = (float*)(smem + OFF_W1);
    float* b1s = (float*)(smem + OFF_B1);
    float* b2s = (float*)(smem + OFF_B2);
    float* b3s = (float*)(smem + OFF_B3);
    float* b4s = (float*)(smem + OFF_B4);
    float* w5s = (float*)(smem + OFF_W5);
    u64* stg_all = (u64*)(smem + OFF_STG);
    u64* xs = (u64*)(smem + OFF_XS);

    const int tid = threadIdx.x;
    const int lane = tid & 31;
    const int warp = tid >> 5;

    // Stage all weights in SMEM once (amortized over 60 steps).
    cpy(w2s, w2g, HD * HD, tid);
    cpy(w3s, w3g, HD * HD, tid);
    cpy(w4s, w4g, HD * HD, tid);
    cpy(w1s, w1g, 2 * HD, tid);
    cpy(b1s, b1g, HD, tid);
    cpy(b2s, b2g, HD, tid);
    cpy(b3s, b3g, HD, tid);
    cpy(b4s, b4g, HD, tid);
    cpy(w5s, w5g, HD, tid);

    const int cbase = blockIdx.x * CH_PER_CTA + warp * (PAIRS * 2);

    if (lane == 0) {
#pragma unroll
        for (int p = 0; p < PAIRS; p++) {
            int c0 = cbase + 2 * p;
            float4 xi = *(const float4*)(x0g + (size_t)c0 * 2);
            xs[(warp * PAIRS + p) * 2 + 0] = pk(xi.x, xi.z);   // x-components of pair
            xs[(warp * PAIRS + p) * 2 + 1] = pk(xi.y, xi.w);   // y-components of pair
        }
    }
    __syncthreads();

    u64* stg = stg_all + warp * (PAIRS * 3 * HD);
    const int j0 = lane * 4;

    for (int t = 0; t < NSTEPS; t++) {
        // ---- layer 1: 2 -> 128, Jacobian rows of z1 are rows of W1 ----
#pragma unroll
        for (int p = 0; p < PAIRS; p++) {
            u64 xp = xs[(warp * PAIRS + p) * 2 + 0];
            u64 yp = xs[(warp * PAIRS + p) * 2 + 1];
            u64 ho[4], xo[4], yo[4];
#pragma unroll
            for (int u = 0; u < 4; u++) {
                int j = j0 + u;
                float wa = w1s[j], wb = w1s[HD + j];
                u64 z = fma2(xp, dup(wa), fma2(yp, dup(wb), dup(b1s[j])));
                u64 h, d;
                silu2(z, h, d);
                ho[u] = h;
                xo[u] = mul2(d, dup(wa));
                yo[u] = mul2(d, dup(wb));
            }
            st4(stg + (p * 3 + 0) * HD + j0, ho);
            st4(stg + (p * 3 + 1) * HD + j0, xo);
            st4(stg + (p * 3 + 2) * HD + j0, yo);
        }
        __syncwarp();

        u64 pg[PAIRS][2];
#pragma unroll
        for (int p = 0; p < PAIRS; p++) { pg[p][0] = 0ull; pg[p][1] = 0ull; }

        dense<false>(w2s, b2s, w5s, stg, j0, pg);
        dense<false>(w3s, b3s, w5s, stg, j0, pg);
        dense<true >(w4s, b4s, w5s, stg, j0, pg);

        // ---- per-pair warp reduction of grad partials ----
        float gv[PAIRS][2][2];
#pragma unroll
        for (int p = 0; p < PAIRS; p++)
#pragma unroll
            for (int c = 0; c < 2; c++) {
                float a, b;
                upk(pg[p][c], a, b);
#pragma unroll
                for (int m = 16; m > 0; m >>= 1) {
                    a += __shfl_xor_sync(0xffffffffu, a, m);
                    b += __shfl_xor_sync(0xffffffffu, b, m);
                }
                gv[p][c][0] = a;
                gv[p][c][1] = b;
            }

        float fi = (float)t;
        float eps = 10.0f * (1.0f - fi / 60.0f);
        float cn = sqrtf(2.0f * eps) * 0.005f;

        if (lane == 0) {
#pragma unroll
            for (int p = 0; p < PAIRS; p++) {
                int c0 = cbase + 2 * p;
                float4 nz = *(const float4*)(noise + ((size_t)t * NCH + c0) * 2);
                float xa, xb, ya, yb;
                upk(xs[(warp * PAIRS + p) * 2 + 0], xa, xb);
                upk(xs[(warp * PAIRS + p) * 2 + 1], ya, yb);
                float g00 = fminf(fmaxf(gv[p][0][0], -0.03f), 0.03f);
                float g10 = fminf(fmaxf(gv[p][1][0], -0.03f), 0.03f);
                float g01 = fminf(fmaxf(gv[p][0][1], -0.03f), 0.03f);
                float g11 = fminf(fmaxf(gv[p][1][1], -0.03f), 0.03f);
                xa = fminf(fmaxf(xa + cn * nz.x + eps * g00, -2.43f), 3.05f);
                ya = fminf(fmaxf(ya + cn * nz.y + eps * g10, -2.43f), 3.05f);
                xb = fminf(fmaxf(xb + cn * nz.z + eps * g01, -2.43f), 3.05f);
                yb = fminf(fmaxf(yb + cn * nz.w + eps * g11, -2.43f), 3.05f);
                xs[(warp * PAIRS + p) * 2 + 0] = pk(xa, xb);
                xs[(warp * PAIRS + p) * 2 + 1] = pk(ya, yb);
            }
        }
        __syncwarp();
    }

    // ---- write final x ----
    if (lane == 0) {
#pragma unroll
        for (int p = 0; p < PAIRS; p++) {
            int c0 = cbase + 2 * p;
            float xa, xb, ya, yb;
            upk(xs[(warp * PAIRS + p) * 2 + 0], xa, xb);
            upk(xs[(warp * PAIRS + p) * 2 + 1], ya, yb);
            float4 o;
            o.x = xa; o.y = ya; o.z = xb; o.w = yb;
            *(float4*)(out + (size_t)c0 * 2) = o;
        }
    }
}

extern "C" void kernel_launch(void* const* d_in, const int* in_sizes, int n_in,
                              void* d_out, int out_size) {
    const float* x0 = (const float*)d_in[0];
    const float* w1 = (const float*)d_in[1];
    const float* b1 = (const float*)d_in[2];
    const float* w2 = (const float*)d_in[3];
    const float* b2 = (const float*)d_in[4];
    const float* w3 = (const float*)d_in[5];
    const float* b3 = (const float*)d_in[6];
    const float* w4 = (const float*)d_in[7];
    const float* b4 = (const float*)d_in[8];
    const float* w5 = (const float*)d_in[9];
    // d_in[10] = b5 (additive constant, does not affect grad) — unused
    const float* noise = (const float*)d_in[11];
    float* out = (float*)d_out;

    cudaFuncSetAttribute(EBMb_17360257810670_kernel,
                         cudaFuncAttributeMaxDynamicSharedMemorySize, SMEM_BYTES);
    EBMb_17360257810670_kernel<<<GRID, THREADS, SMEM_BYTES>>>(
        x0, w1, b1, w2, b2, w3, b3, w4, b4, w5, noise, out);
}